// round 5
// baseline (speedup 1.0000x reference)
#include <cuda_runtime.h>

#define NTIME   4096
#define NBATCH  4096
#define NEXTRA  256
#define COLS    4                  // batch columns per CTA
#define THREADS 256
#define OPT     ((NEXTRA * COLS) / THREADS)   // outputs per thread = 4
#define INTERP_ITERS 6

__global__ __launch_bounds__(THREADS, 3)
void interp_kernel(const float* __restrict__ times,
                   const float* __restrict__ values,
                   const float* __restrict__ t,
                   float* __restrict__ out)
{
    extern __shared__ float s_times[];   // row-major [NTIME][COLS], 64 KB

    const int b0  = blockIdx.x * COLS;
    const int tid = threadIdx.x;

    // ---- Stage times[:, b0:b0+4]: float4 row -> float4 smem, no transpose ----
    {
        const float4* tg = reinterpret_cast<const float4*>(times + b0);
        float4*       sg = reinterpret_cast<float4*>(s_times);
        #pragma unroll 4
        for (int i = tid; i < NTIME; i += THREADS)
            sg[i] = tg[(size_t)i * (NBATCH / 4)];
    }
    __syncthreads();

    // ---- Per-thread mapping: all OPT outputs share one column ----
    const int    c    = tid & (COLS - 1);
    const int    qb   = tid >> 2;                 // base query row; +64 per k
    const float* vcol = values + b0 + c;

    const float a0 = s_times[0 * COLS + c];               // times[0, col]
    const float aN = s_times[(NTIME - 1) * COLS + c];     // times[-1, col]

    int   oidx[OPT];
    float tq[OPT];
    int   lo[OPT], hi[OPT];
    float alo[OPT], ahi[OPT];

    #pragma unroll
    for (int k = 0; k < OPT; k++) {
        int q   = qb + k * (THREADS / COLS);
        oidx[k] = q * NBATCH + b0 + c;
        tq[k]   = t[oidx[k]];
        lo[k] = 0;          hi[k] = NTIME - 1;
        alo[k] = a0;        ahi[k] = aN;
    }

    // ---- Interpolation search: find last j with times[j] <= tq ----
    // Invariants: alo == times[lo] <= tq (t >= times[0] by construction),
    //             ahi == times[hi], and times[hi] > tq once hi has been probed.
    #pragma unroll
    for (int it = 0; it < INTERP_ITERS; it++) {
        #pragma unroll
        for (int k = 0; k < OPT; k++) {
            if (hi[k] - lo[k] > 1) {
                float frac = __fdividef(tq[k] - alo[k], ahi[k] - alo[k]);
                int   m    = lo[k] + 1 + (int)(frac * (float)(hi[k] - lo[k] - 1));
                m = max(m, lo[k] + 1);
                m = min(m, hi[k] - 1);
                float am = s_times[m * COLS + c];
                bool  le = (am <= tq[k]);
                lo[k]  = le ? m  : lo[k];
                alo[k] = le ? am : alo[k];
                hi[k]  = le ? hi[k] : m;
                ahi[k] = le ? ahi[k] : am;
            }
        }
    }
    // Guaranteed-terminating bisection cleanup (rarely entered)
    #pragma unroll
    for (int k = 0; k < OPT; k++) {
        while (hi[k] - lo[k] > 1) {
            int   m  = (lo[k] + hi[k]) >> 1;
            float am = s_times[m * COLS + c];
            if (am <= tq[k]) { lo[k] = m; }
            else             { hi[k] = m; ahi[k] = am; }
        }
    }

    // ---- Interpolate ----
    #pragma unroll
    for (int k = 0; k < OPT; k++) {
        int j     = (ahi[k] <= tq[k]) ? hi[k] : lo[k];   // last index with times[j] <= tq
        int count = j + 1;                               // searchsorted 'right'
        int gi    = (count == NTIME) ? 0 : count;        // count % NTIME
        int sidx  = (gi == 0) ? (NTIME - 2) : (gi - 1);  // slope index (len NTIME-1)
        // t0/v0 index: gi==0 -> sidx+1 (torch -1 wrap), else sidx
        float tlo = s_times[sidx * COLS + c];
        float thi = s_times[(sidx + 1) * COLS + c];

        float vlo = __ldg(vcol + (size_t)sidx * NBATCH);
        float vhi = __ldg(vcol + (size_t)(sidx + 1) * NBATCH);

        float t0 = (gi == 0) ? thi : tlo;
        float v0 = (gi == 0) ? vhi : vlo;
        float s0 = (vhi - vlo) / (thi - tlo);
        out[oidx[k]] = v0 + s0 * (tq[k] - t0);
    }
}

extern "C" void kernel_launch(void* const* d_in, const int* in_sizes, int n_in,
                              void* d_out, int out_size)
{
    const float* times  = (const float*)d_in[0];
    const float* values = (const float*)d_in[1];
    const float* t      = (const float*)d_in[2];
    float*       out    = (float*)d_out;

    size_t smem = (size_t)NTIME * COLS * sizeof(float);   // 65,536 B
    cudaFuncSetAttribute(interp_kernel,
                         cudaFuncAttributeMaxDynamicSharedMemorySize, (int)smem);
    interp_kernel<<<NBATCH / COLS, THREADS, smem>>>(times, values, t, out);
}

// round 7
// speedup vs baseline: 1.3107x; 1.3107x over previous
#include <cuda_runtime.h>

#define NTIME   4096
#define NBATCH  4096
#define NEXTRA  256
#define COLS    4
#define THREADS 256
#define OPT     ((NEXTRA * COLS) / THREADS)   // 4 outputs per thread
#define CSTEP   16
#define NCOARSE 257                           // entry i -> row min(16*i, 4095)
#define CSTRIDE 260

__global__ __launch_bounds__(THREADS)
void interp_kernel(const float* __restrict__ times,
                   const float* __restrict__ values,
                   const float* __restrict__ t,
                   float* __restrict__ out)
{
    __shared__ float s_coarse[COLS][CSTRIDE];

    const int b0  = blockIdx.x * COLS;
    const int tid = threadIdx.x;

    // ---- Stage coarse table: one float4 (this CTA's 4 columns) per sampled row ----
    for (int r = tid; r < NCOARSE; r += THREADS) {
        int row = r * CSTEP;
        if (row > NTIME - 1) row = NTIME - 1;
        float4 v = *reinterpret_cast<const float4*>(times + (size_t)row * NBATCH + b0);
        s_coarse[0][r] = v.x;
        s_coarse[1][r] = v.y;
        s_coarse[2][r] = v.z;
        s_coarse[3][r] = v.w;
    }
    __syncthreads();

    const int    c    = tid & (COLS - 1);
    const int    qb   = tid >> 2;               // +64 per k
    const int    bcol = b0 + c;
    const float* sc   = s_coarse[c];
    const float* tcol = times  + bcol;
    const float* vcol = values + bcol;

    int   oidx[OPT];
    float tq[OPT];
    int   lo[OPT], hi[OPT];
    float alo[OPT], ahi[OPT];

    #pragma unroll
    for (int k = 0; k < OPT; k++) {
        int q   = qb + k * (THREADS / COLS);
        oidx[k] = q * NBATCH + bcol;
        tq[k]   = t[oidx[k]];
    }

    // ---- Coarse binary search over 257 SMEM entries: max p with coarse[p] <= tq ----
    int pos[OPT];
    #pragma unroll
    for (int k = 0; k < OPT; k++) pos[k] = 0;
    #pragma unroll
    for (int step = 256; step >= 1; step >>= 1) {
        #pragma unroll
        for (int k = 0; k < OPT; k++) {
            int np = pos[k] + step;
            if (np < NCOARSE && sc[np] <= tq[k]) pos[k] = np;
        }
    }
    #pragma unroll
    for (int k = 0; k < OPT; k++) {
        int p  = pos[k];
        lo[k]  = (p * CSTEP > NTIME - 1) ? (NTIME - 1) : p * CSTEP;
        int hr = (p + 1) * CSTEP;
        hi[k]  = (hr > NTIME - 1) ? (NTIME - 1) : hr;
        alo[k] = sc[p];
        ahi[k] = (p < NCOARSE - 1) ? sc[p + 1] : alo[k];
    }

    // ---- Fine search: interpolation probes in GMEM (bracket width <= 16) ----
    // Invariant: alo == times[lo] <= tq, ahi == times[hi] > tq (while hi > lo+1).
    #pragma unroll
    for (int it = 0; it < 2; it++) {          // batched passes: OPT probes in flight
        int   m[OPT];
        float am[OPT];
        bool  act[OPT];
        #pragma unroll
        for (int k = 0; k < OPT; k++) {
            act[k] = (hi[k] - lo[k] > 1);
            if (act[k]) {
                float frac = __fdividef(tq[k] - alo[k], ahi[k] - alo[k]);
                int   mm   = lo[k] + 1 + (int)(frac * (float)(hi[k] - lo[k] - 1));
                mm   = max(mm, lo[k] + 1);
                mm   = min(mm, hi[k] - 1);
                m[k]  = mm;
                am[k] = __ldg(tcol + (size_t)mm * NBATCH);
            }
        }
        #pragma unroll
        for (int k = 0; k < OPT; k++) {
            if (act[k]) {
                bool le = (am[k] <= tq[k]);
                lo[k]  = le ? m[k]  : lo[k];
                alo[k] = le ? am[k] : alo[k];
                hi[k]  = le ? hi[k] : m[k];
                ahi[k] = le ? ahi[k] : am[k];   // FIXED: upper bound moves only on !le
            }
        }
    }
    // Cleanup (rare): guaranteed-terminating hybrid loop
    #pragma unroll
    for (int k = 0; k < OPT; k++) {
        while (hi[k] - lo[k] > 1) {
            float frac = __fdividef(tq[k] - alo[k], ahi[k] - alo[k]);
            int   mm   = lo[k] + 1 + (int)(frac * (float)(hi[k] - lo[k] - 1));
            mm = max(mm, lo[k] + 1);
            mm = min(mm, hi[k] - 1);
            float am = __ldg(tcol + (size_t)mm * NBATCH);
            if (am <= tq[k]) { lo[k] = mm; alo[k] = am; }
            else             { hi[k] = mm; ahi[k] = am; }
        }
    }

    // ---- Interpolate: count = lo+1; times[lo] <= tq < times[lo+1] ----
    #pragma unroll
    for (int k = 0; k < OPT; k++) {
        int   j     = lo[k];
        int   count = j + 1;
        int   wrap  = (count == NTIME);          // tq >= times[-1]: ~never, but exact
        int   sidx;
        float tlo, thi;
        if (wrap) {
            sidx = NTIME - 2;
            thi  = alo[k];                       // times[4095]
            tlo  = __ldg(tcol + (size_t)(NTIME - 2) * NBATCH);
        } else {
            sidx = j;
            tlo  = alo[k];                       // times[j]
            thi  = ahi[k];                       // times[j+1]
        }
        float vlo = __ldg(vcol + (size_t)sidx * NBATCH);
        float vhi = __ldg(vcol + (size_t)(sidx + 1) * NBATCH);

        float t0 = wrap ? thi : tlo;
        float v0 = wrap ? vhi : vlo;
        float s0 = (vhi - vlo) / (thi - tlo);
        out[oidx[k]] = v0 + s0 * (tq[k] - t0);
    }
}

extern "C" void kernel_launch(void* const* d_in, const int* in_sizes, int n_in,
                              void* d_out, int out_size)
{
    const float* times  = (const float*)d_in[0];
    const float* values = (const float*)d_in[1];
    const float* t      = (const float*)d_in[2];
    float*       out    = (float*)d_out;

    interp_kernel<<<NBATCH / COLS, THREADS>>>(times, values, t, out);
}

// round 10
// speedup vs baseline: 1.3495x; 1.0296x over previous
#include <cuda_runtime.h>

#define NTIME   4096
#define NBATCH  4096
#define NEXTRA  256
#define COLS    4
#define THREADS 256
#define OPT     4                 // outputs per thread
#define CSTEP   8
#define NCOARSE 513               // entry p -> row min(8p, 4095)
#define CSTRIDE 516               // floats; 516*4 B % 16 == 0 (keeps every row 16B-aligned)
#define WS_MAX  496               // max window start; multiple of 4 (LDS.128-aligned)

__global__ __launch_bounds__(THREADS)
void interp_kernel(const float* __restrict__ times,
                   const float* __restrict__ values,
                   const float* __restrict__ t,
                   float* __restrict__ out)
{
    __shared__ __align__(16) float s_coarse[COLS][CSTRIDE];   // 16B base for LDS.128

    const int b0  = blockIdx.x * COLS;
    const int tid = threadIdx.x;

    // ---- Stage coarse table: one float4 (4 columns) per sampled row ----
    for (int r = tid; r < NCOARSE; r += THREADS) {
        int row = min(r * CSTEP, NTIME - 1);
        float4 v = *reinterpret_cast<const float4*>(times + (size_t)row * NBATCH + b0);
        s_coarse[0][r] = v.x;
        s_coarse[1][r] = v.y;
        s_coarse[2][r] = v.z;
        s_coarse[3][r] = v.w;
    }
    __syncthreads();

    const int    c    = tid & (COLS - 1);
    const int    qb   = tid >> 2;               // +64 per k
    const int    bcol = b0 + c;
    const float* sc   = s_coarse[c];
    const float* tcol = times  + bcol;
    const float* vcol = values + bcol;

    const float a0   = sc[0];
    const float aN   = sc[NCOARSE - 1];
    const float invr = 1.0f / (aN - a0);        // strictly increasing -> finite

    int   oidx[OPT];
    float tq[OPT];
    int   lo[OPT], hi[OPT];
    float alo[OPT], ahi[OPT];

    #pragma unroll
    for (int k = 0; k < OPT; k++) {
        int q   = qb + k * (THREADS / COLS);
        oidx[k] = q * NBATCH + bcol;
        tq[k]   = t[oidx[k]];
    }

    // ---- Coarse: predict slot, verify with a 16-entry SMEM window (1 LDS round) ----
    #pragma unroll
    for (int k = 0; k < OPT; k++) {
        float tk = tq[k];
        int p0 = (int)((tk - a0) * invr * (float)(NCOARSE - 1));
        p0 = min(max(p0, 0), NCOARSE - 1);
        int ws = (p0 - 7) & ~3;                 // multiple of 4
        ws = min(max(ws, 0), WS_MAX);           // WS_MAX multiple of 4 -> LDS.128 aligned
        const float4* s4 = reinterpret_cast<const float4*>(sc + ws);
        float4 w0 = s4[0], w1 = s4[1], w2 = s4[2], w3 = s4[3];
        int cnt = (w0.x <= tk) + (w0.y <= tk) + (w0.z <= tk) + (w0.w <= tk)
                + (w1.x <= tk) + (w1.y <= tk) + (w1.z <= tk) + (w1.w <= tk)
                + (w2.x <= tk) + (w2.y <= tk) + (w2.z <= tk) + (w2.w <= tk)
                + (w3.x <= tk) + (w3.y <= tk) + (w3.z <= tk) + (w3.w <= tk);
        int p;
        if (cnt == 0 || cnt == 16) {            // boundary outside window: full binary search
            p = 0;
            #pragma unroll
            for (int step = 512; step >= 1; step >>= 1) {
                int np = p + step;
                if (np < NCOARSE && sc[np] <= tk) p = np;
            }
        } else {
            p = ws + cnt - 1;                   // sc[p] <= tk < sc[p+1]
        }
        lo[k]  = min(p * CSTEP, NTIME - 1);
        hi[k]  = min((p + 1) * CSTEP, NTIME - 1);
        alo[k] = sc[p];
        ahi[k] = (p < NCOARSE - 1) ? sc[p + 1] : alo[k];
    }

    // ---- Fine round 1: paired probe m, m+1 (batched, one memory round) ----
    // Invariant: alo == times[lo] <= tq; ahi == times[hi] > tq while hi > lo.
    {
        int   m[OPT];
        float am[OPT], am1[OPT];
        bool  act[OPT];
        #pragma unroll
        for (int k = 0; k < OPT; k++) {
            act[k] = (hi[k] - lo[k] > 1);
            if (act[k]) {
                float frac = __fdividef(tq[k] - alo[k], ahi[k] - alo[k]);
                int   mm   = lo[k] + 1 + (int)(frac * (float)(hi[k] - lo[k] - 1));
                mm   = min(max(mm, lo[k] + 1), hi[k] - 1);
                m[k] = mm;
                am[k]  = __ldg(tcol + (size_t)mm * NBATCH);
                am1[k] = (mm + 1 <= hi[k] - 1) ? __ldg(tcol + (size_t)(mm + 1) * NBATCH)
                                               : ahi[k];
            }
        }
        #pragma unroll
        for (int k = 0; k < OPT; k++) {
            if (act[k]) {
                if (am[k] <= tq[k]) {
                    if (tq[k] < am1[k]) {                       // resolved: j = m
                        lo[k] = m[k];     alo[k] = am[k];
                        hi[k] = m[k] + 1; ahi[k] = am1[k];
                    } else {                                     // j > m; am1 is a real probe
                        lo[k] = m[k] + 1; alo[k] = am1[k];
                    }
                } else {                                         // j < m
                    hi[k] = m[k];         ahi[k] = am[k];
                }
            }
        }
    }
    // ---- Cleanup: guaranteed-terminating hybrid loop (rare) ----
    #pragma unroll
    for (int k = 0; k < OPT; k++) {
        while (hi[k] - lo[k] > 1) {
            float frac = __fdividef(tq[k] - alo[k], ahi[k] - alo[k]);
            int   mm   = lo[k] + 1 + (int)(frac * (float)(hi[k] - lo[k] - 1));
            mm = min(max(mm, lo[k] + 1), hi[k] - 1);
            float am = __ldg(tcol + (size_t)mm * NBATCH);
            if (am <= tq[k]) { lo[k] = mm; alo[k] = am; }
            else             { hi[k] = mm; ahi[k] = am; }
        }
    }

    // ---- Interpolate: count = lo+1; times[lo] <= tq < times[lo+1] ----
    #pragma unroll
    for (int k = 0; k < OPT; k++) {
        int   j     = lo[k];
        int   wrap  = (j + 1 == NTIME);          // tq >= times[-1]
        int   sidx;
        float tlo, thi;
        if (wrap) {
            sidx = NTIME - 2;
            thi  = alo[k];                       // times[4095]
            tlo  = __ldg(tcol + (size_t)(NTIME - 2) * NBATCH);
        } else {
            sidx = j;
            tlo  = alo[k];                       // times[j]
            thi  = ahi[k];                       // times[j+1]
        }
        float vlo = __ldg(vcol + (size_t)sidx * NBATCH);
        float vhi = __ldg(vcol + (size_t)(sidx + 1) * NBATCH);

        float t0 = wrap ? thi : tlo;
        float v0 = wrap ? vhi : vlo;
        float s0 = (vhi - vlo) / (thi - tlo);
        out[oidx[k]] = v0 + s0 * (tq[k] - t0);
    }
}

extern "C" void kernel_launch(void* const* d_in, const int* in_sizes, int n_in,
                              void* d_out, int out_size)
{
    const float* times  = (const float*)d_in[0];
    const float* values = (const float*)d_in[1];
    const float* t      = (const float*)d_in[2];
    float*       out    = (float*)d_out;

    interp_kernel<<<NBATCH / COLS, THREADS>>>(times, values, t, out);
}